// round 4
// baseline (speedup 1.0000x reference)
#include <cuda_runtime.h>
#include <cstdint>

// ---------------------------------------------------------------------------
// HeteroGAT — CSR-gather GAT + 3xTF32 tensor-core GEMMs + Wal logit refactor
// ---------------------------------------------------------------------------

#define NAUT   16384
#define NPAP   16384
#define IN_DIM 128
#define HID    64
#define NHEAD  4
#define OUTF   349
#define NEDGE  262144
#define NNODE  16384
#define NEG_SLOPE 0.2f

constexpr long long NHF = (long long)NNODE * HID;
constexpr long long N4  = (long long)NNODE * NHEAD;

constexpr long long OFF_FA0   = 0;
constexpr long long OFF_FP1   = OFF_FA0 + NHF;
constexpr long long OFF_FP2   = OFF_FP1 + NHF;
constexpr long long OFF_F1A   = OFF_FP2 + NHF;
constexpr long long OFF_F1PC  = OFF_F1A + NHF;
constexpr long long OFF_OUTP  = OFF_F1PC + NHF;
constexpr long long OFF_OUTP1 = OFF_OUTP + NHF;
constexpr long long OFF_HA1   = OFF_OUTP1 + NHF;
constexpr long long OFF_HP1   = OFF_HA1 + NHF;
constexpr long long OFF_HF    = OFF_HP1 + NHF;
constexpr long long OFF_ELER  = OFF_HF + 2 * NHF;      // 10 x N4
constexpr long long OFF_WAL   = OFF_ELER + 10 * N4;    // 10 x 128 x 4
constexpr long long OFF_C     = OFF_WAL + 10 * 512;
constexpr long long OFF_DEG   = OFF_C + 4;             // ints below
constexpr long long OFF_RP    = OFF_DEG + 3LL * NNODE;
constexpr long long OFF_CSR   = OFF_RP + 3LL * (NNODE + 1);
constexpr long long SCRATCH_TOTAL = OFF_CSR + 3LL * NEDGE + 16;

__device__ float g_scratch[SCRATCH_TOTAL];

__device__ __forceinline__ float leaky(float x) {
    return x > 0.f ? x : NEG_SLOPE * x;
}

// ---------------------------------------------------------------------------
// CSR build
// ---------------------------------------------------------------------------
__global__ void zero_int_kernel(int* __restrict__ p, int n) {
    int i = blockIdx.x * blockDim.x + threadIdx.x;
    if (i < n) p[i] = 0;
}

__global__ void hist3_kernel(const int* __restrict__ d0, const int* __restrict__ d1,
                             const int* __restrict__ d2, int* __restrict__ deg) {
    int t = blockIdx.x * blockDim.x + threadIdx.x;
    if (t >= 3 * NEDGE) return;
    int g = t >> 18;
    int e = t & (NEDGE - 1);
    const int* ds = (g == 0) ? d0 : (g == 1) ? d1 : d2;
    atomicAdd(&deg[g * NNODE + ds[e]], 1);
}

__global__ __launch_bounds__(1024) void scan3_kernel(int* __restrict__ deg,
                                                     int* __restrict__ rp) {
    __shared__ int sh[1024];
    int t = threadIdx.x;
    int g = blockIdx.x;
    int* dg = deg + g * NNODE;
    int* r  = rp + g * (NNODE + 1);
    int loc[16];
    int run = 0;
    int base = t * 16;
#pragma unroll
    for (int i = 0; i < 16; i++) { loc[i] = run; run += dg[base + i]; }
    sh[t] = run;
    __syncthreads();
    for (int d = 1; d < 1024; d <<= 1) {
        int v = sh[t];
        int a = (t >= d) ? sh[t - d] : 0;
        __syncthreads();
        sh[t] = v + a;
        __syncthreads();
    }
    int off = (t == 0) ? 0 : sh[t - 1];
#pragma unroll
    for (int i = 0; i < 16; i++) {
        int v = off + loc[i];
        r[base + i] = v;
        dg[base + i] = v;
    }
    if (t == 1023) r[NNODE] = off + run;
}

__global__ void scatter3_kernel(const int* __restrict__ s0, const int* __restrict__ d0,
                                const int* __restrict__ s1, const int* __restrict__ d1,
                                const int* __restrict__ s2, const int* __restrict__ d2,
                                int* __restrict__ cur, int* __restrict__ csr) {
    int t = blockIdx.x * blockDim.x + threadIdx.x;
    if (t >= 3 * NEDGE) return;
    int g = t >> 18;
    int e = t & (NEDGE - 1);
    const int* ss = (g == 0) ? s0 : (g == 1) ? s1 : s2;
    const int* ds = (g == 0) ? d0 : (g == 1) ? d1 : d2;
    int d = ds[e];
    int pos = atomicAdd(&cur[g * NNODE + d], 1);
    csr[(long long)g * NEDGE + pos] = ss[e];
}

// ---------------------------------------------------------------------------
// TF32 helpers
// ---------------------------------------------------------------------------
__device__ __forceinline__ void split_tf32(float v, float& hi, float& lo) {
    uint32_t hb; asm("cvt.rna.tf32.f32 %0, %1;" : "=r"(hb) : "f"(v));
    hi = __uint_as_float(hb);
    float l = v - hi;
    uint32_t lb; asm("cvt.rna.tf32.f32 %0, %1;" : "=r"(lb) : "f"(l));
    lo = __uint_as_float(lb);
}

#define MMA_TF32(d, a0, a1, a2, a3, b0, b1)                                      \
    asm volatile("mma.sync.aligned.m16n8k8.row.col.f32.tf32.tf32.f32 "           \
                 "{%0,%1,%2,%3}, {%4,%5,%6,%7}, {%8,%9}, {%0,%1,%2,%3};"         \
                 : "+f"((d).x), "+f"((d).y), "+f"((d).z), "+f"((d).w)            \
                 : "r"(__float_as_uint(a0)), "r"(__float_as_uint(a1)),           \
                   "r"(__float_as_uint(a2)), "r"(__float_as_uint(a3)),           \
                   "r"(__float_as_uint(b0)), "r"(__float_as_uint(b1)))

// ---------------------------------------------------------------------------
// Batched 3xTF32 GEMM: C[16384,64] = (A .* colscale) @ W[K,64]
// Block 128x64, 8 warps (warp tile 32x32), BK=16.
// ---------------------------------------------------------------------------
struct GemmJob { const float* A; const float* sc; const float* W; float* C; };
struct Gemm3 { GemmJob j[3]; int K; };

__global__ __launch_bounds__(256) void gemm_tf32_kernel(Gemm3 p) {
    GemmJob jb = p.j[blockIdx.y];
    const int K = p.K;
    __shared__ float Ah[128][20], Al[128][20];   // pad 20: frag banks r*20+k -> r*4+k mod 32
    __shared__ float Wh[16][72], Wl[16][72];     // pad 72: frag banks k*8+n
    int tid = threadIdx.x;
    int wid = tid >> 5, lane = tid & 31;
    int warpM = wid & 3, warpN = wid >> 2;
    int g = lane >> 2, t4 = lane & 3;
    int row0 = blockIdx.x * 128;
    float4 acc[2][4] = {};

    for (int kt = 0; kt < K; kt += 16) {
#pragma unroll
        for (int i = 0; i < 8; i++) {            // A: 128x16
            int idx = tid + i * 256;
            int r = idx >> 4, k = idx & 15;
            float v = jb.A[(long long)(row0 + r) * K + kt + k];
            if (jb.sc) v *= jb.sc[kt + k];
            float hi, lo; split_tf32(v, hi, lo);
            Ah[r][k] = hi; Al[r][k] = lo;
        }
#pragma unroll
        for (int i = 0; i < 4; i++) {            // W: 16x64
            int idx = tid + i * 256;
            int k = idx >> 6, c = idx & 63;
            float v = jb.W[(long long)(kt + k) * 64 + c];
            float hi, lo; split_tf32(v, hi, lo);
            Wh[k][c] = hi; Wl[k][c] = lo;
        }
        __syncthreads();
#pragma unroll
        for (int kk = 0; kk < 2; kk++) {
            int k8 = kk * 8;
            float bh[4][2], bl[4][2];
#pragma unroll
            for (int ni = 0; ni < 4; ni++) {
                int n = warpN * 32 + ni * 8 + g;
                bh[ni][0] = Wh[k8 + t4][n];     bh[ni][1] = Wh[k8 + t4 + 4][n];
                bl[ni][0] = Wl[k8 + t4][n];     bl[ni][1] = Wl[k8 + t4 + 4][n];
            }
#pragma unroll
            for (int mi = 0; mi < 2; mi++) {
                int r = warpM * 32 + mi * 16;
                float ah0 = Ah[r + g][k8 + t4],     ah1 = Ah[r + g + 8][k8 + t4];
                float ah2 = Ah[r + g][k8 + t4 + 4], ah3 = Ah[r + g + 8][k8 + t4 + 4];
                float al0 = Al[r + g][k8 + t4],     al1 = Al[r + g + 8][k8 + t4];
                float al2 = Al[r + g][k8 + t4 + 4], al3 = Al[r + g + 8][k8 + t4 + 4];
#pragma unroll
                for (int ni = 0; ni < 4; ni++) {
                    MMA_TF32(acc[mi][ni], ah0, ah1, ah2, ah3, bh[ni][0], bh[ni][1]);
                    MMA_TF32(acc[mi][ni], ah0, ah1, ah2, ah3, bl[ni][0], bl[ni][1]);
                    MMA_TF32(acc[mi][ni], al0, al1, al2, al3, bh[ni][0], bh[ni][1]);
                }
            }
        }
        __syncthreads();
    }
#pragma unroll
    for (int mi = 0; mi < 2; mi++) {
        long long rb = row0 + warpM * 32 + mi * 16 + g;
#pragma unroll
        for (int ni = 0; ni < 4; ni++) {
            int c = warpN * 32 + ni * 8 + 2 * t4;
            float4 v = acc[mi][ni];
            *(float2*)&jb.C[rb * 64 + c] = make_float2(v.x, v.y);
            *(float2*)&jb.C[(rb + 8) * 64 + c] = make_float2(v.z, v.w);
        }
    }
}

// ---- full 3xTF32 GEMM with bias + arbitrary Ncols (final projection) ----
__global__ __launch_bounds__(256) void gemm_tf32_full_kernel(
    const float* __restrict__ A, const float* __restrict__ W,
    const float* __restrict__ bias, float* __restrict__ C,
    int K, int Ncols) {
    __shared__ float Ah[128][20], Al[128][20];
    __shared__ float Wh[16][72], Wl[16][72];
    int tid = threadIdx.x;
    int wid = tid >> 5, lane = tid & 31;
    int warpM = wid & 3, warpN = wid >> 2;
    int g = lane >> 2, t4 = lane & 3;
    int row0 = blockIdx.x * 128;
    int col0 = blockIdx.y * 64;
    float4 acc[2][4] = {};

    for (int kt = 0; kt < K; kt += 16) {
#pragma unroll
        for (int i = 0; i < 8; i++) {
            int idx = tid + i * 256;
            int r = idx >> 4, k = idx & 15;
            float v = A[(long long)(row0 + r) * K + kt + k];
            float hi, lo; split_tf32(v, hi, lo);
            Ah[r][k] = hi; Al[r][k] = lo;
        }
#pragma unroll
        for (int i = 0; i < 4; i++) {
            int idx = tid + i * 256;
            int k = idx >> 6, c = idx & 63;
            int gc = col0 + c;
            float v = (gc < Ncols) ? W[(long long)(kt + k) * Ncols + gc] : 0.0f;
            float hi, lo; split_tf32(v, hi, lo);
            Wh[k][c] = hi; Wl[k][c] = lo;
        }
        __syncthreads();
#pragma unroll
        for (int kk = 0; kk < 2; kk++) {
            int k8 = kk * 8;
            float bh[4][2], bl[4][2];
#pragma unroll
            for (int ni = 0; ni < 4; ni++) {
                int n = warpN * 32 + ni * 8 + g;
                bh[ni][0] = Wh[k8 + t4][n];     bh[ni][1] = Wh[k8 + t4 + 4][n];
                bl[ni][0] = Wl[k8 + t4][n];     bl[ni][1] = Wl[k8 + t4 + 4][n];
            }
#pragma unroll
            for (int mi = 0; mi < 2; mi++) {
                int r = warpM * 32 + mi * 16;
                float ah0 = Ah[r + g][k8 + t4],     ah1 = Ah[r + g + 8][k8 + t4];
                float ah2 = Ah[r + g][k8 + t4 + 4], ah3 = Ah[r + g + 8][k8 + t4 + 4];
                float al0 = Al[r + g][k8 + t4],     al1 = Al[r + g + 8][k8 + t4];
                float al2 = Al[r + g][k8 + t4 + 4], al3 = Al[r + g + 8][k8 + t4 + 4];
#pragma unroll
                for (int ni = 0; ni < 4; ni++) {
                    MMA_TF32(acc[mi][ni], ah0, ah1, ah2, ah3, bh[ni][0], bh[ni][1]);
                    MMA_TF32(acc[mi][ni], ah0, ah1, ah2, ah3, bl[ni][0], bl[ni][1]);
                    MMA_TF32(acc[mi][ni], al0, al1, al2, al3, bh[ni][0], bh[ni][1]);
                }
            }
        }
        __syncthreads();
    }
#pragma unroll
    for (int mi = 0; mi < 2; mi++) {
        long long rb = row0 + warpM * 32 + mi * 16 + g;
#pragma unroll
        for (int ni = 0; ni < 4; ni++) {
            int c = col0 + warpN * 32 + ni * 8 + 2 * t4;
            float4 v = acc[mi][ni];
            if (c < Ncols) {
                C[rb * Ncols + c] = v.x + bias[c];
                C[(rb + 8) * Ncols + c] = v.z + bias[c];
            }
            if (c + 1 < Ncols) {
                C[rb * Ncols + c + 1] = v.y + bias[c + 1];
                C[(rb + 8) * Ncols + c + 1] = v.w + bias[c + 1];
            }
        }
    }
}

// ---------------------------------------------------------------------------
// Wal precompute: Wal[m][k][h] = sc_m[k] * sum_d W_m[k][h*16+d] * a_m[h*16+d]
// (folds node-type scaling and the attention vector into one KxH matrix so
//  attention logits come straight from the raw inputs in full fp32)
// ---------------------------------------------------------------------------
struct WalSpec {
    const float* W[10];
    const float* a[10];
    const float* sc[10];
    int K[10];
};

__global__ void wal_kernel(WalSpec p, float* __restrict__ wal) {
    int i = blockIdx.x * blockDim.x + threadIdx.x;
    if (i >= 10 * 512) return;
    int m = i >> 9;
    int r = i & 511;
    int k = r >> 2, h = r & 3;
    float v = 0.f;
    if (k < p.K[m]) {
        const float* Wr = p.W[m] + (long long)k * 64 + h * 16;
        const float* ar = p.a[m] + h * 16;
        float s = 0.f;
#pragma unroll
        for (int d = 0; d < 16; d++) s += Wr[d] * ar[d];
        v = s * (p.sc[m] ? p.sc[m][k] : 1.0f);
    }
    wal[i] = v;
}

// ---------------------------------------------------------------------------
// elgemm: out_v[n][h] = sum_k X[n][k] * Wal_v[k][h], batched over 2 jobs.
// Block handles 64 nodes; thread = (node, head); loops over variants.
// ---------------------------------------------------------------------------
struct ElB {
    const float* X[2];
    const float* Wal[2];   // base of contiguous [nvar][128][4] region
    int nvar[2];
    float* out[2][4];
};

__global__ __launch_bounds__(256) void elgemm_kernel(ElB p, int K, int kshift) {
    __shared__ float tile[64 * 129];           // stride K+1 (<=129)
    __shared__ float sWal[4 * 512];
    int job = blockIdx.y;
    const float* X = p.X[job];
    int nvar = p.nvar[job];
    int tid = threadIdx.x;
    int node0 = blockIdx.x * 64;
    int stride = K + 1;

    for (int idx = tid; idx < 64 * K; idx += 256) {
        int r = idx >> kshift, k = idx & (K - 1);
        tile[r * stride + k] = X[(long long)(node0 + r) * K + k];
    }
    for (int idx = tid; idx < nvar * 512; idx += 256)
        sWal[idx] = p.Wal[job][idx];
    __syncthreads();

    int n = tid >> 2, h = tid & 3;
    const float* trow = tile + n * stride;
    for (int v = 0; v < nvar; v++) {
        const float* wv = sWal + v * 512 + h;
        float s = 0.f;
#pragma unroll 4
        for (int k = 0; k < K; k++) s += trow[k] * wv[k * 4];
        p.out[job][v][(node0 + n) * 4 + h] = s;
    }
}

// ---------------------------------------------------------------------------
// Fused GAT (round-2 proven version): one warp per destination node.
// ---------------------------------------------------------------------------
#define MERGE(m, s)                                                        \
    {                                                                      \
        float om = __shfl_xor_sync(0xFFFFFFFFu, (m), off);                 \
        float os = __shfl_xor_sync(0xFFFFFFFFu, (s), off);                 \
        float nm = fmaxf((m), om);                                         \
        (s) = (s) * __expf((m) - nm) + os * __expf(om - nm);               \
        (m) = nm;                                                          \
    }

__global__ __launch_bounds__(256) void gat_kernel(
    const int* __restrict__ rp, const int* __restrict__ csr,
    const float* __restrict__ el, const float* __restrict__ er,
    const float* __restrict__ fs, const float* __restrict__ prev,
    const float* __restrict__ ba, const float* __restrict__ bb,
    int do_relu, float* __restrict__ out) {
    int w = (blockIdx.x * blockDim.x + threadIdx.x) >> 5;
    int lane = threadIdx.x & 31;
    if (w >= NNODE) return;
    int d = w;
    int beg = rp[d], end = rp[d + 1];
    float4 er4 = *(const float4*)(er + 4 * d);

    float m0 = -1e30f, m1 = -1e30f, m2 = -1e30f, m3 = -1e30f;
    float s0 = 0.f, s1 = 0.f, s2 = 0.f, s3 = 0.f;
    for (int i = beg + lane; i < end; i += 32) {
        int s = csr[i];
        float4 l4 = *(const float4*)(el + 4 * s);
        float e0 = leaky(l4.x + er4.x);
        float e1 = leaky(l4.y + er4.y);
        float e2 = leaky(l4.z + er4.z);
        float e3 = leaky(l4.w + er4.w);
        float nm;
        nm = fmaxf(m0, e0); s0 = s0 * __expf(m0 - nm) + __expf(e0 - nm); m0 = nm;
        nm = fmaxf(m1, e1); s1 = s1 * __expf(m1 - nm) + __expf(e1 - nm); m1 = nm;
        nm = fmaxf(m2, e2); s2 = s2 * __expf(m2 - nm) + __expf(e2 - nm); m2 = nm;
        nm = fmaxf(m3, e3); s3 = s3 * __expf(m3 - nm) + __expf(e3 - nm); m3 = nm;
    }
#pragma unroll
    for (int off = 16; off; off >>= 1) {
        MERGE(m0, s0) MERGE(m1, s1) MERGE(m2, s2) MERGE(m3, s3)
    }
    float inv0 = 1.f / fmaxf(s0, 1e-9f);
    float inv1 = 1.f / fmaxf(s1, 1e-9f);
    float inv2 = 1.f / fmaxf(s2, 1e-9f);
    float inv3 = 1.f / fmaxf(s3, 1e-9f);

    bool hi = (lane & 16) != 0;
    float mA = hi ? m1 : m0, iA = hi ? inv1 : inv0, eA = hi ? er4.y : er4.x;
    float mB = hi ? m3 : m2, iB = hi ? inv3 : inv2, eB = hi ? er4.w : er4.z;
    float acc0 = 0.f, acc1 = 0.f;
    for (int i = beg; i < end; i++) {
        int s = csr[i];
        float4 l4 = *(const float4*)(el + 4 * s);
        float lA = hi ? l4.y : l4.x;
        float lB = hi ? l4.w : l4.z;
        float w0 = __expf(leaky(lA + eA) - mA) * iA;
        float w1 = __expf(leaky(lB + eB) - mB) * iB;
        const float* fr = fs + (long long)s * HID;
        acc0 += fr[lane] * w0;
        acc1 += fr[lane + 32] * w1;
    }
    long long ob = (long long)d * HID;
    if (prev) { acc0 += prev[ob + lane]; acc1 += prev[ob + lane + 32]; }
    if (ba)   { acc0 += ba[lane];        acc1 += ba[lane + 32]; }
    if (bb)   { acc0 += bb[lane];        acc1 += bb[lane + 32]; }
    if (do_relu) { acc0 = fmaxf(acc0, 0.f); acc1 = fmaxf(acc1, 0.f); }
    out[ob + lane] = acc0;
    out[ob + lane + 32] = acc1;
}

// ---------------------------------------------------------------------------
// Collapsed per-node transformer (size-1 feature axis => layernorm == bias)
// ---------------------------------------------------------------------------
__global__ void compute_C_kernel(const float* ln1_gb, const float* attn_w, const float* attn_b,
                                 const float* ln2_gb, const float* ffn_w1, const float* ffn_b1,
                                 const float* ffn_w2, const float* ffn_b2, float* out) {
    float y1 = ln1_gb[1];
    float v = y1 * attn_w[2] + attn_b[2];
    float o = v * attn_w[3] + attn_b[3];
    float y2 = ln2_gb[1];
    float f = ffn_b2[0];
    for (int j = 0; j < 16; j++) {
        float z = y2 * ffn_w1[j] + ffn_b1[j];
        float g = 0.5f * z * (1.0f + erff(z * 0.70710678118654752f));
        f += g * ffn_w2[j];
    }
    out[0] = o + f;
}

__global__ void hf_kernel(const float* __restrict__ acc, const float* __restrict__ b1,
                          const float* __restrict__ Cs, float* __restrict__ hf) {
    int g = blockIdx.x * blockDim.x + threadIdx.x;
    int row = g >> 5;
    int lane = g & 31;
    if (row >= NPAP) return;
    float C = Cs[0];
    long long base = (long long)row * HID;
    float v0 = acc[base + lane]      + b1[lane]      + b1[64 + lane];
    float v1 = acc[base + lane + 32] + b1[lane + 32] + b1[96 + lane];
    float w0 = v0 + C, w1 = v1 + C;
    float s1 = v0 * v0 + v1 * v1;
    float s2 = w0 * w0 + w1 * w1;
#pragma unroll
    for (int o = 16; o; o >>= 1) {
        s1 += __shfl_xor_sync(0xFFFFFFFFu, s1, o);
        s2 += __shfl_xor_sync(0xFFFFFFFFu, s2, o);
    }
    float i1 = 1.f / fmaxf(sqrtf(s1), 1e-12f);
    float i2 = 1.f / fmaxf(sqrtf(s2), 1e-12f);
    long long hb = (long long)row * 128;
    hf[hb + lane]       = v0 * i1;
    hf[hb + lane + 32]  = v1 * i1;
    hf[hb + 64 + lane]  = w0 * i2;
    hf[hb + 96 + lane]  = w1 * i2;
}

// ---------------------------------------------------------------------------
extern "C" void kernel_launch(void* const* d_in, const int* in_sizes, int n_in,
                              void* d_out, int out_size) {
    const float* x_author = (const float*)d_in[0];
    const float* x_paper  = (const float*)d_in[1];
    const float* ntype    = (const float*)d_in[2];
    const float* W0       = (const float*)d_in[3];
    const float* al0      = (const float*)d_in[4];
    const float* ar0      = (const float*)d_in[5];
    const float* b0       = (const float*)d_in[6];
    const float* W1       = (const float*)d_in[7];
    const float* al1      = (const float*)d_in[8];
    const float* ar1      = (const float*)d_in[9];
    const float* b1       = (const float*)d_in[10];
    const float* ln1_gb   = (const float*)d_in[11];
    const float* attn_w   = (const float*)d_in[12];
    const float* attn_b   = (const float*)d_in[13];
    const float* ln2_gb   = (const float*)d_in[14];
    const float* ffn_w1   = (const float*)d_in[15];
    const float* ffn_b1   = (const float*)d_in[16];
    const float* ffn_w2   = (const float*)d_in[17];
    const float* ffn_b2   = (const float*)d_in[18];
    const float* lin_W    = (const float*)d_in[19];
    const float* lin_b    = (const float*)d_in[20];
    const int* src_w = (const int*)d_in[21];
    const int* dst_w = (const int*)d_in[22];
    const int* src_c = (const int*)d_in[23];
    const int* dst_c = (const int*)d_in[24];
    const int* src_r = (const int*)d_in[25];
    const int* dst_r = (const int*)d_in[26];
    float* out = (float*)d_out;

    float* S = nullptr;
    cudaGetSymbolAddress((void**)&S, g_scratch);

    float* Fa0   = S + OFF_FA0;
    float* Fp1   = S + OFF_FP1;
    float* Fp2   = S + OFF_FP2;
    float* F1a   = S + OFF_F1A;
    float* F1pc  = S + OFF_F1PC;
    float* outp  = S + OFF_OUTP;
    float* outp1 = S + OFF_OUTP1;
    float* ha1   = S + OFF_HA1;
    float* hp1   = S + OFF_HP1;
    float* hf    = S + OFF_HF;
    float* wal   = S + OFF_WAL;
    // el/er arrays in Wal mat order
    float* el_w  = S + OFF_ELER + 0 * N4;   // mat0 (ha)
    float* er_r  = S + OFF_ELER + 1 * N4;   // mat1 (ha)
    float* er_w  = S + OFF_ELER + 2 * N4;   // mat2 (hp)
    float* el_c  = S + OFF_ELER + 3 * N4;   // mat3 (hp)
    float* er_c  = S + OFF_ELER + 4 * N4;   // mat4 (hp)
    float* el_r  = S + OFF_ELER + 5 * N4;   // mat5 (hp)
    float* el1w  = S + OFF_ELER + 6 * N4;   // mat6 (ha1)
    float* er1w  = S + OFF_ELER + 7 * N4;   // mat7 (hp1)
    float* el1c  = S + OFF_ELER + 8 * N4;   // mat8 (hp1)
    float* er1c  = S + OFF_ELER + 9 * N4;   // mat9 (hp1)
    float* Cscalar = S + OFF_C;
    int* degB = (int*)(S + OFF_DEG);
    int* rpB  = (int*)(S + OFF_RP);
    int* csrB = (int*)(S + OFF_CSR);

    const int T = 256;
    const float* nt0 = ntype;
    const float* nt1 = ntype + IN_DIM;

    // ---- CSR build ----
    zero_int_kernel<<<(3 * NNODE + T - 1) / T, T>>>(degB, 3 * NNODE);
    hist3_kernel<<<(3 * NEDGE + T - 1) / T, T>>>(dst_w, dst_c, dst_r, degB);
    scan3_kernel<<<3, 1024>>>(degB, rpB);
    scatter3_kernel<<<(3 * NEDGE + T - 1) / T, T>>>(src_w, dst_w, src_c, dst_c,
                                                    src_r, dst_r, degB, csrB);
    const int* rp_w = rpB + 0 * (NNODE + 1);
    const int* rp_c = rpB + 1 * (NNODE + 1);
    const int* rp_r = rpB + 2 * (NNODE + 1);
    const int* csr_w = csrB + 0LL * NEDGE;
    const int* csr_c = csrB + 1LL * NEDGE;
    const int* csr_r = csrB + 2LL * NEDGE;

    // ---- Wal (all 10 logit matrices, weights only) ----
    WalSpec ws;
    ws.W[0] = W0 + 0 * 8192; ws.a[0] = al0 + 0 * 64; ws.sc[0] = nt0; ws.K[0] = 128; // el_w
    ws.W[1] = W0 + 2 * 8192; ws.a[1] = ar0 + 2 * 64; ws.sc[1] = nt0; ws.K[1] = 128; // er_r
    ws.W[2] = W0 + 0 * 8192; ws.a[2] = ar0 + 0 * 64; ws.sc[2] = nt1; ws.K[2] = 128; // er_w
    ws.W[3] = W0 + 1 * 8192; ws.a[3] = al0 + 1 * 64; ws.sc[3] = nt1; ws.K[3] = 128; // el_c
    ws.W[4] = W0 + 1 * 8192; ws.a[4] = ar0 + 1 * 64; ws.sc[4] = nt1; ws.K[4] = 128; // er_c
    ws.W[5] = W0 + 2 * 8192; ws.a[5] = al0 + 2 * 64; ws.sc[5] = nt1; ws.K[5] = 128; // el_r
    ws.W[6] = W1 + 0 * 4096; ws.a[6] = al1 + 0 * 64; ws.sc[6] = nullptr; ws.K[6] = 64; // el1w
    ws.W[7] = W1 + 0 * 4096; ws.a[7] = ar1 + 0 * 64; ws.sc[7] = nullptr; ws.K[7] = 64; // er1w
    ws.W[8] = W1 + 1 * 4096; ws.a[8] = al1 + 1 * 64; ws.sc[8] = nullptr; ws.K[8] = 64; // el1c
    ws.W[9] = W1 + 1 * 4096; ws.a[9] = ar1 + 1 * 64; ws.sc[9] = nullptr; ws.K[9] = 64; // er1c
    wal_kernel<<<20, 256>>>(ws, wal);

    // ---- layer 0 feature GEMMs (only gathered matrices needed) ----
    Gemm3 g0;
    g0.j[0] = { x_author, nt0, W0 + 0 * 8192, Fa0 };
    g0.j[1] = { x_paper,  nt1, W0 + 1 * 8192, Fp1 };
    g0.j[2] = { x_paper,  nt1, W0 + 2 * 8192, Fp2 };
    g0.K = IN_DIM;
    gemm_tf32_kernel<<<dim3(NNODE / 128, 3), 256>>>(g0);

    // ---- layer 0 logits straight from raw inputs ----
    ElB e0;
    e0.X[0] = x_author; e0.Wal[0] = wal + 0 * 512; e0.nvar[0] = 2;
    e0.out[0][0] = el_w; e0.out[0][1] = er_r; e0.out[0][2] = nullptr; e0.out[0][3] = nullptr;
    e0.X[1] = x_paper;  e0.Wal[1] = wal + 2 * 512; e0.nvar[1] = 4;
    e0.out[1][0] = er_w; e0.out[1][1] = el_c; e0.out[1][2] = er_c; e0.out[1][3] = el_r;
    elgemm_kernel<<<dim3(NNODE / 64, 2), 256>>>(e0, 128, 7);

    unsigned gb = (NNODE * 32) / T;
    gat_kernel<<<gb, T>>>(rp_w, csr_w, el_w, er_w, Fa0, nullptr, nullptr, nullptr, 0, outp);
    gat_kernel<<<gb, T>>>(rp_r, csr_r, el_r, er_r, Fp2, nullptr, b0 + 128, nullptr, 1, ha1);
    gat_kernel<<<gb, T>>>(rp_c, csr_c, el_c, er_c, Fp1, outp, b0, b0 + 64, 1, hp1);

    // ---- layer 1 feature GEMMs ----
    Gemm3 g1;
    g1.j[0] = { ha1, nullptr, W1 + 0 * 4096, F1a };
    g1.j[1] = { hp1, nullptr, W1 + 1 * 4096, F1pc };
    g1.j[2] = { nullptr, nullptr, nullptr, nullptr };
    g1.K = HID;
    gemm_tf32_kernel<<<dim3(NNODE / 128, 2), 256>>>(g1);

    ElB e1;
    e1.X[0] = ha1; e1.Wal[0] = wal + 6 * 512; e1.nvar[0] = 1;
    e1.out[0][0] = el1w; e1.out[0][1] = nullptr; e1.out[0][2] = nullptr; e1.out[0][3] = nullptr;
    e1.X[1] = hp1; e1.Wal[1] = wal + 7 * 512; e1.nvar[1] = 3;
    e1.out[1][0] = er1w; e1.out[1][1] = el1c; e1.out[1][2] = er1c; e1.out[1][3] = nullptr;
    elgemm_kernel<<<dim3(NNODE / 64, 2), 256>>>(e1, 64, 6);

    gat_kernel<<<gb, T>>>(rp_w, csr_w, el1w, er1w, F1a, nullptr, nullptr, nullptr, 0, outp1);
    gat_kernel<<<gb, T>>>(rp_c, csr_c, el1c, er1c, F1pc, outp1, nullptr, nullptr, 0, outp1);

    // ---- collapsed transformer scalar + normalized concat ----
    compute_C_kernel<<<1, 1>>>(ln1_gb, attn_w, attn_b, ln2_gb,
                               ffn_w1, ffn_b1, ffn_w2, ffn_b2, Cscalar);
    hf_kernel<<<(NPAP * 32) / T, T>>>(outp1, b1, Cscalar, hf);

    // ---- final projection (3xTF32) ----
    gemm_tf32_full_kernel<<<dim3(NPAP / 128, (OUTF + 63) / 64), 256>>>(
        hf, lin_W, lin_b, out, 2 * HID, OUTF);
}

// round 5
// speedup vs baseline: 1.1835x; 1.1835x over previous
#include <cuda_runtime.h>

// ---------------------------------------------------------------------------
// HeteroGAT — R2 kernel bodies, restructured DAG:
//  co-launched independent stages + batched GATs + fused epilogues
// ---------------------------------------------------------------------------

#define NNODE  16384
#define IN_DIM 128
#define HID    64
#define OUTF   349
#define NEDGE  262144
#define NEG_SLOPE 0.2f

constexpr long long NHF = (long long)NNODE * HID;
constexpr long long N4  = (long long)NNODE * 4;

constexpr long long OFF_FA0   = 0;
constexpr long long OFF_FP0   = OFF_FA0 + NHF;
constexpr long long OFF_FP1   = OFF_FP0 + NHF;
constexpr long long OFF_FP2   = OFF_FP1 + NHF;
constexpr long long OFF_FA2   = OFF_FP2 + NHF;
constexpr long long OFF_F1A   = OFF_FA2 + NHF;
constexpr long long OFF_F1PD  = OFF_F1A + NHF;
constexpr long long OFF_F1PC  = OFF_F1PD + NHF;
constexpr long long OFF_OUTPW = OFF_F1PC + NHF;
constexpr long long OFF_OUTPC = OFF_OUTPW + NHF;
constexpr long long OFF_O1W   = OFF_OUTPC + NHF;
constexpr long long OFF_O1C   = OFF_O1W + NHF;
constexpr long long OFF_HA1   = OFF_O1C + NHF;
constexpr long long OFF_HF    = OFF_HA1 + NHF;
constexpr long long OFF_ELER  = OFF_HF + 2 * NHF;       // 10 x N4
constexpr long long OFF_DEG   = OFF_ELER + 10 * N4;     // ints below
constexpr long long OFF_RP    = OFF_DEG + 3LL * NNODE;
constexpr long long OFF_CSR   = OFF_RP + 3LL * (NNODE + 1);
constexpr long long SCRATCH_TOTAL = OFF_CSR + 3LL * NEDGE + 16;

__device__ float g_scratch[SCRATCH_TOTAL];

__device__ __forceinline__ float leaky(float x) {
    return x > 0.f ? x : NEG_SLOPE * x;
}

// ---------------------------------------------------------------------------
// small kernels
// ---------------------------------------------------------------------------
__global__ void zero_int_kernel(int* __restrict__ p, int n) {
    int i = blockIdx.x * blockDim.x + threadIdx.x;
    if (i < n) p[i] = 0;
}

__global__ __launch_bounds__(1024) void scan3_kernel(int* __restrict__ deg,
                                                     int* __restrict__ rp) {
    __shared__ int sh[1024];
    int t = threadIdx.x;
    int g = blockIdx.x;
    int* dg = deg + g * NNODE;
    int* r  = rp + g * (NNODE + 1);
    int loc[16];
    int run = 0;
    int base = t * 16;
#pragma unroll
    for (int i = 0; i < 16; i++) { loc[i] = run; run += dg[base + i]; }
    sh[t] = run;
    __syncthreads();
    for (int d = 1; d < 1024; d <<= 1) {
        int v = sh[t];
        int a = (t >= d) ? sh[t - d] : 0;
        __syncthreads();
        sh[t] = v + a;
        __syncthreads();
    }
    int off = (t == 0) ? 0 : sh[t - 1];
#pragma unroll
    for (int i = 0; i < 16; i++) {
        int v = off + loc[i];
        r[base + i] = v;
        dg[base + i] = v;
    }
    if (t == 1023) r[NNODE] = off + run;
}

// ---------------------------------------------------------------------------
// GEMM body (R2-proven 64x64 tile, 4x4 micro-tile) with optional fused A-prep
// ---------------------------------------------------------------------------
struct GJob {
    const float* A;      // primary input
    const float* A2;     // optional second matrix (added)
    const float* scale;  // optional per-col scale
    const float* ab0;    // optional per-col bias
    const float* ab1;    // optional per-col bias 2
    int relu;            // relu after combine
    const float* W;
    float* C;
};
struct GBatch { GJob j[5]; int K; };

__device__ __forceinline__ void gemm64_body(const GJob jb, int K, int tile, int tid) {
    __shared__ __align__(16) float As[64][65];
    __shared__ __align__(16) float Ws[64][64];
    int row0 = tile * 64;
    int tr = (tid >> 4) * 4;
    int tc = (tid & 15) * 4;
    float acc[4][4] = {};
    for (int kt = 0; kt < K; kt += 64) {
#pragma unroll
        for (int i = 0; i < 16; i++) {
            int idx = tid + i * 256;
            int r = idx >> 6, k = idx & 63;
            int kc = kt + k;
            long long off = (long long)(row0 + r) * K + kc;
            float v = jb.A[off];
            if (jb.scale) v *= jb.scale[kc];
            if (jb.A2)    v += jb.A2[off];
            if (jb.ab0)   v += jb.ab0[kc];
            if (jb.ab1)   v += jb.ab1[kc];
            if (jb.relu)  v = fmaxf(v, 0.f);
            As[k][r] = v;
        }
#pragma unroll
        for (int i = 0; i < 16; i++) {
            int idx = tid + i * 256;
            int k = idx >> 6, c = idx & 63;
            Ws[k][c] = jb.W[(long long)(kt + k) * 64 + c];
        }
        __syncthreads();
#pragma unroll 16
        for (int k = 0; k < 64; k++) {
            float a0 = As[k][tr], a1 = As[k][tr + 1], a2 = As[k][tr + 2], a3 = As[k][tr + 3];
            float4 w = *(const float4*)&Ws[k][tc];
            acc[0][0] += a0 * w.x; acc[0][1] += a0 * w.y; acc[0][2] += a0 * w.z; acc[0][3] += a0 * w.w;
            acc[1][0] += a1 * w.x; acc[1][1] += a1 * w.y; acc[1][2] += a1 * w.z; acc[1][3] += a1 * w.w;
            acc[2][0] += a2 * w.x; acc[2][1] += a2 * w.y; acc[2][2] += a2 * w.z; acc[2][3] += a2 * w.w;
            acc[3][0] += a3 * w.x; acc[3][1] += a3 * w.y; acc[3][2] += a3 * w.z; acc[3][3] += a3 * w.w;
        }
        __syncthreads();
    }
#pragma unroll
    for (int i = 0; i < 4; i++) {
        long long r = row0 + tr + i;
#pragma unroll
        for (int j = 0; j < 4; j++)
            jb.C[r * 64 + tc + j] = acc[i][j];
    }
}

__global__ __launch_bounds__(256) void gemm64_kernel(GBatch p) {
    gemm64_body(p.j[blockIdx.y], p.K, blockIdx.x, threadIdx.x);
}

// ---------------------------------------------------------------------------
// eler body (R2-proven)
// ---------------------------------------------------------------------------
struct EJob { const float* F; const float* a; float* out; };
struct E6 { EJob j[6]; };

__device__ __forceinline__ void eler_body(const EJob p, int i) {
    int node = i >> 2, h = i & 3;
    const float4* f = (const float4*)(p.F + (long long)node * HID + h * 16);
    const float4* a = (const float4*)(p.a + h * 16);
    float s = 0.f;
#pragma unroll
    for (int j = 0; j < 4; j++) {
        float4 fv = f[j], av = a[j];
        s += fv.x * av.x + fv.y * av.y + fv.z * av.z + fv.w * av.w;
    }
    p.out[i] = s;
}

__global__ void eler_kernel(E6 p) {
    eler_body(p.j[blockIdx.y], blockIdx.x * blockDim.x + threadIdx.x);
}

// ---------------------------------------------------------------------------
// combined launches: hist+gemm5, scatter+eler6
// ---------------------------------------------------------------------------
__global__ __launch_bounds__(256) void hist_gemm_kernel(
    const int* __restrict__ d0, const int* __restrict__ d1, const int* __restrict__ d2,
    int* __restrict__ deg, GBatch p) {
    if (blockIdx.x < 3072) {
        int t = blockIdx.x * 256 + threadIdx.x;     // < 3*NEDGE exactly
        int g = t >> 18;
        int e = t & (NEDGE - 1);
        const int* ds = (g == 0) ? d0 : (g == 1) ? d1 : d2;
        atomicAdd(&deg[g * NNODE + ds[e]], 1);
    } else {
        int b = blockIdx.x - 3072;
        gemm64_body(p.j[b >> 8], p.K, b & 255, threadIdx.x);
    }
}

__global__ __launch_bounds__(256) void scatter_eler_kernel(
    const int* __restrict__ s0, const int* __restrict__ d0,
    const int* __restrict__ s1, const int* __restrict__ d1,
    const int* __restrict__ s2, const int* __restrict__ d2,
    int* __restrict__ cur, int* __restrict__ csr, E6 p) {
    if (blockIdx.x < 3072) {
        int t = blockIdx.x * 256 + threadIdx.x;
        int g = t >> 18;
        int e = t & (NEDGE - 1);
        const int* ss = (g == 0) ? s0 : (g == 1) ? s1 : s2;
        const int* ds = (g == 0) ? d0 : (g == 1) ? d1 : d2;
        int d = ds[e];
        int pos = atomicAdd(&cur[g * NNODE + d], 1);
        csr[(long long)g * NEDGE + pos] = ss[e];
    } else {
        int b = blockIdx.x - 3072;
        eler_body(p.j[b >> 8], (b & 255) * 256 + threadIdx.x);
    }
}

// ---------------------------------------------------------------------------
// Fused GAT (R2-proven, 1 warp/node), batched over independent jobs
// ---------------------------------------------------------------------------
struct GatJob {
    const int* rp; const int* csr;
    const float* el; const float* er; const float* fs;
    const float* ba; int relu;
    float* out;
};
struct GatB { GatJob j[3]; };

#define MERGE(m, s)                                                        \
    {                                                                      \
        float om = __shfl_xor_sync(0xFFFFFFFFu, (m), off);                 \
        float os = __shfl_xor_sync(0xFFFFFFFFu, (s), off);                 \
        float nm = fmaxf((m), om);                                         \
        (s) = (s) * __expf((m) - nm) + os * __expf(om - nm);               \
        (m) = nm;                                                          \
    }

__global__ __launch_bounds__(256) void gat_kernel(GatB p) {
    GatJob jb = p.j[blockIdx.y];
    int w = (blockIdx.x * blockDim.x + threadIdx.x) >> 5;
    int lane = threadIdx.x & 31;
    if (w >= NNODE) return;
    int d = w;
    int beg = jb.rp[d], end = jb.rp[d + 1];
    float4 er4 = *(const float4*)(jb.er + 4 * d);

    float m0 = -1e30f, m1 = -1e30f, m2 = -1e30f, m3 = -1e30f;
    float s0 = 0.f, s1 = 0.f, s2 = 0.f, s3 = 0.f;
    for (int i = beg + lane; i < end; i += 32) {
        int s = jb.csr[i];
        float4 l4 = *(const float4*)(jb.el + 4 * s);
        float e0 = leaky(l4.x + er4.x);
        float e1 = leaky(l4.y + er4.y);
        float e2 = leaky(l4.z + er4.z);
        float e3 = leaky(l4.w + er4.w);
        float nm;
        nm = fmaxf(m0, e0); s0 = s0 * __expf(m0 - nm) + __expf(e0 - nm); m0 = nm;
        nm = fmaxf(m1, e1); s1 = s1 * __expf(m1 - nm) + __expf(e1 - nm); m1 = nm;
        nm = fmaxf(m2, e2); s2 = s2 * __expf(m2 - nm) + __expf(e2 - nm); m2 = nm;
        nm = fmaxf(m3, e3); s3 = s3 * __expf(m3 - nm) + __expf(e3 - nm); m3 = nm;
    }
#pragma unroll
    for (int off = 16; off; off >>= 1) {
        MERGE(m0, s0) MERGE(m1, s1) MERGE(m2, s2) MERGE(m3, s3)
    }
    float inv0 = 1.f / fmaxf(s0, 1e-9f);
    float inv1 = 1.f / fmaxf(s1, 1e-9f);
    float inv2 = 1.f / fmaxf(s2, 1e-9f);
    float inv3 = 1.f / fmaxf(s3, 1e-9f);

    bool hi = (lane & 16) != 0;
    float mA = hi ? m1 : m0, iA = hi ? inv1 : inv0, eA = hi ? er4.y : er4.x;
    float mB = hi ? m3 : m2, iB = hi ? inv3 : inv2, eB = hi ? er4.w : er4.z;
    float acc0 = 0.f, acc1 = 0.f;
    for (int i = beg; i < end; i++) {
        int s = jb.csr[i];
        float4 l4 = *(const float4*)(jb.el + 4 * s);
        float lA = hi ? l4.y : l4.x;
        float lB = hi ? l4.w : l4.z;
        float w0 = __expf(leaky(lA + eA) - mA) * iA;
        float w1 = __expf(leaky(lB + eB) - mB) * iB;
        const float* fr = jb.fs + (long long)s * HID;
        acc0 += fr[lane] * w0;
        acc1 += fr[lane + 32] * w1;
    }
    long long ob = (long long)d * HID;
    if (jb.ba) { acc0 += jb.ba[lane]; acc1 += jb.ba[lane + 32]; }
    if (jb.relu) { acc0 = fmaxf(acc0, 0.f); acc1 = fmaxf(acc1, 0.f); }
    jb.out[ob + lane] = acc0;
    jb.out[ob + lane + 32] = acc1;
}

// ---------------------------------------------------------------------------
// hf: sums the two layer-1 GAT partials, adds biases + scalar C (computed
// inline — _ln over the size-1 feature axis equals its bias exactly),
// then writes [l2norm(h1), l2norm(h1+C)].
// ---------------------------------------------------------------------------
__global__ __launch_bounds__(256) void hf_kernel(
    const float* __restrict__ accW, const float* __restrict__ accC,
    const float* __restrict__ b1,
    const float* __restrict__ ln1_gb, const float* __restrict__ attn_w,
    const float* __restrict__ attn_b, const float* __restrict__ ln2_gb,
    const float* __restrict__ ffn_w1, const float* __restrict__ ffn_b1,
    const float* __restrict__ ffn_w2, const float* __restrict__ ffn_b2,
    float* __restrict__ hf) {
    __shared__ float sC;
    if (threadIdx.x == 0) {
        float y1 = ln1_gb[1];
        float v = y1 * attn_w[2] + attn_b[2];
        float o = v * attn_w[3] + attn_b[3];
        float y2 = ln2_gb[1];
        float f = ffn_b2[0];
        for (int j = 0; j < 16; j++) {
            float z = y2 * ffn_w1[j] + ffn_b1[j];
            float g = 0.5f * z * (1.0f + erff(z * 0.70710678118654752f));
            f += g * ffn_w2[j];
        }
        sC = o + f;
    }
    __syncthreads();
    float C = sC;

    int g = blockIdx.x * blockDim.x + threadIdx.x;
    int row = g >> 5;
    int lane = g & 31;
    if (row >= NNODE) return;
    long long base = (long long)row * HID;
    float v0 = accW[base + lane]      + accC[base + lane]
             + b1[lane]      + b1[64 + lane];
    float v1 = accW[base + lane + 32] + accC[base + lane + 32]
             + b1[lane + 32] + b1[96 + lane];
    float w0 = v0 + C, w1 = v1 + C;
    float s1 = v0 * v0 + v1 * v1;
    float s2 = w0 * w0 + w1 * w1;
#pragma unroll
    for (int o = 16; o; o >>= 1) {
        s1 += __shfl_xor_sync(0xFFFFFFFFu, s1, o);
        s2 += __shfl_xor_sync(0xFFFFFFFFu, s2, o);
    }
    float i1 = 1.f / fmaxf(sqrtf(s1), 1e-12f);
    float i2 = 1.f / fmaxf(sqrtf(s2), 1e-12f);
    long long hb = (long long)row * 128;
    hf[hb + lane]       = v0 * i1;
    hf[hb + lane + 32]  = v1 * i1;
    hf[hb + 64 + lane]  = w0 * i2;
    hf[hb + 96 + lane]  = w1 * i2;
}

// ---- full GEMM (R2-proven) for the final projection ----
__global__ __launch_bounds__(256) void gemm_full_kernel(
    const float* __restrict__ A, const float* __restrict__ W,
    const float* __restrict__ bias, float* __restrict__ C,
    int K, int Ncols) {
    __shared__ __align__(16) float As[64][65];
    __shared__ __align__(16) float Ws[64][64];
    int row0 = blockIdx.x * 64;
    int col0 = blockIdx.y * 64;
    int tid = threadIdx.x;
    int tr = (tid >> 4) * 4;
    int tc = (tid & 15) * 4;
    float acc[4][4] = {};
    for (int kt = 0; kt < K; kt += 64) {
#pragma unroll
        for (int i = 0; i < 16; i++) {
            int idx = tid + i * 256;
            int r = idx >> 6, k = idx & 63;
            As[k][r] = A[(long long)(row0 + r) * K + kt + k];
        }
#pragma unroll
        for (int i = 0; i < 16; i++) {
            int idx = tid + i * 256;
            int k = idx >> 6, c = idx & 63;
            int gc = col0 + c;
            Ws[k][c] = (gc < Ncols) ? W[(long long)(kt + k) * Ncols + gc] : 0.0f;
        }
        __syncthreads();
#pragma unroll 16
        for (int k = 0; k < 64; k++) {
            float a0 = As[k][tr], a1 = As[k][tr + 1], a2 = As[k][tr + 2], a3 = As[k][tr + 3];
            float4 w = *(const float4*)&Ws[k][tc];
            acc[0][0] += a0 * w.x; acc[0][1] += a0 * w.y; acc[0][2] += a0 * w.z; acc[0][3] += a0 * w.w;
            acc[1][0] += a1 * w.x; acc[1][1] += a1 * w.y; acc[1][2] += a1 * w.z; acc[1][3] += a1 * w.w;
            acc[2][0] += a2 * w.x; acc[2][1] += a2 * w.y; acc[2][2] += a2 * w.z; acc[2][3] += a2 * w.w;
            acc[3][0] += a3 * w.x; acc[3][1] += a3 * w.y; acc[3][2] += a3 * w.z; acc[3][3] += a3 * w.w;
        }
        __syncthreads();
    }
#pragma unroll
    for (int i = 0; i < 4; i++) {
        long long r = row0 + tr + i;
#pragma unroll
        for (int j = 0; j < 4; j++) {
            int c = col0 + tc + j;
            if (c < Ncols) C[r * Ncols + c] = acc[i][j] + bias[c];
        }
    }
}

// ---------------------------------------------------------------------------
extern "C" void kernel_launch(void* const* d_in, const int* in_sizes, int n_in,
                              void* d_out, int out_size) {
    const float* x_author = (const float*)d_in[0];
    const float* x_paper  = (const float*)d_in[1];
    const float* ntype    = (const float*)d_in[2];
    const float* W0       = (const float*)d_in[3];
    const float* al0      = (const float*)d_in[4];
    const float* ar0      = (const float*)d_in[5];
    const float* b0       = (const float*)d_in[6];
    const float* W1       = (const float*)d_in[7];
    const float* al1      = (const float*)d_in[8];
    const float* ar1      = (const float*)d_in[9];
    const float* b1       = (const float*)d_in[10];
    const float* ln1_gb   = (const float*)d_in[11];
    const float* attn_w   = (const float*)d_in[12];
    const float* attn_b   = (const float*)d_in[13];
    const float* ln2_gb   = (const float*)d_in[14];
    const float* ffn_w1   = (const float*)d_in[15];
    const float* ffn_b1   = (const float*)d_in[16];
    const float* ffn_w2   = (const float*)d_in[17];
    const float* ffn_b2   = (const float*)d_in[18];
    const float* lin_W    = (const float*)d_in[19];
    const float* lin_b    = (const float*)d_in[20];
    const int* src_w = (const int*)d_in[21];
    const int* dst_w = (const int*)d_in[22];
    const int* src_c = (const int*)d_in[23];
    const int* dst_c = (const int*)d_in[24];
    const int* src_r = (const int*)d_in[25];
    const int* dst_r = (const int*)d_in[26];
    float* out = (float*)d_out;

    float* S = nullptr;
    cudaGetSymbolAddress((void**)&S, g_scratch);

    float* Fa0   = S + OFF_FA0;
    float* Fp0   = S + OFF_FP0;
    float* Fp1   = S + OFF_FP1;
    float* Fp2   = S + OFF_FP2;
    float* Fa2   = S + OFF_FA2;
    float* F1a   = S + OFF_F1A;
    float* F1pd  = S + OFF_F1PD;
    float* F1pc  = S + OFF_F1PC;
    float* outpW = S + OFF_OUTPW;
    float* outpC = S + OFF_OUTPC;
    float* o1w   = S + OFF_O1W;
    float* o1c   = S + OFF_O1C;
    float* ha1   = S + OFF_HA1;
    float* hf    = S + OFF_HF;
    float* el_w  = S + OFF_ELER + 0 * N4;
    float* er_w  = S + OFF_ELER + 1 * N4;
    float* el_c  = S + OFF_ELER + 2 * N4;
    float* er_c  = S + OFF_ELER + 3 * N4;
    float* el_r  = S + OFF_ELER + 4 * N4;
    float* er_r  = S + OFF_ELER + 5 * N4;
    float* el1w  = S + OFF_ELER + 6 * N4;
    float* er1w  = S + OFF_ELER + 7 * N4;
    float* el1c  = S + OFF_ELER + 8 * N4;
    float* er1c  = S + OFF_ELER + 9 * N4;
    int* degB = (int*)(S + OFF_DEG);
    int* rpB  = (int*)(S + OFF_RP);
    int* csrB = (int*)(S + OFF_CSR);

    const int* rp_w = rpB + 0 * (NNODE + 1);
    const int* rp_c = rpB + 1 * (NNODE + 1);
    const int* rp_r = rpB + 2 * (NNODE + 1);
    const int* csr_w = csrB + 0LL * NEDGE;
    const int* csr_c = csrB + 1LL * NEDGE;
    const int* csr_r = csrB + 2LL * NEDGE;

    const float* nt0 = ntype;
    const float* nt1 = ntype + IN_DIM;

    // L1: zero CSR counters
    zero_int_kernel<<<192, 256>>>(degB, 3 * NNODE);

    // L2: hist (CSR) + 5 layer-0 GEMMs, co-launched
    GBatch g0;
    g0.j[0] = { x_author, nullptr, nt0, nullptr, nullptr, 0, W0 + 0 * 8192, Fa0 };
    g0.j[1] = { x_paper,  nullptr, nt1, nullptr, nullptr, 0, W0 + 0 * 8192, Fp0 };
    g0.j[2] = { x_paper,  nullptr, nt1, nullptr, nullptr, 0, W0 + 1 * 8192, Fp1 };
    g0.j[3] = { x_paper,  nullptr, nt1, nullptr, nullptr, 0, W0 + 2 * 8192, Fp2 };
    g0.j[4] = { x_author, nullptr, nt0, nullptr, nullptr, 0, W0 + 2 * 8192, Fa2 };
    g0.K = IN_DIM;
    hist_gemm_kernel<<<3072 + 5 * 256, 256>>>(dst_w, dst_c, dst_r, degB, g0);

    // L3: scan (row_ptr + cursors)
    scan3_kernel<<<3, 1024>>>(degB, rpB);

    // L4: scatter (CSR fill) + 6 layer-0 eler jobs, co-launched
    E6 e0;
    e0.j[0] = { Fa0, al0 + 0 * 64, el_w };
    e0.j[1] = { Fp0, ar0 + 0 * 64, er_w };
    e0.j[2] = { Fp1, al0 + 1 * 64, el_c };
    e0.j[3] = { Fp1, ar0 + 1 * 64, er_c };
    e0.j[4] = { Fp2, al0 + 2 * 64, el_r };
    e0.j[5] = { Fa2, ar0 + 2 * 64, er_r };
    scatter_eler_kernel<<<3072 + 6 * 256, 256>>>(src_w, dst_w, src_c, dst_c,
                                                 src_r, dst_r, degB, csrB, e0);

    // L5: all three layer-0 GATs batched (independent outputs)
    GatB ga;
    ga.j[0] = { rp_w, csr_w, el_w, er_w, Fa0, nullptr,  0, outpW };
    ga.j[1] = { rp_c, csr_c, el_c, er_c, Fp1, nullptr,  0, outpC };
    ga.j[2] = { rp_r, csr_r, el_r, er_r, Fp2, b0 + 128, 1, ha1 };
    gat_kernel<<<dim3(2048, 3), 256>>>(ga);

    // L6: 3 layer-1 GEMMs; hp1 = relu(outpW+outpC+b0[0]+b0[1]) fused in A-load
    GBatch g1;
    g1.j[0] = { ha1,   nullptr, nullptr, nullptr, nullptr,  0, W1 + 0 * 4096, F1a };
    g1.j[1] = { outpW, outpC,   nullptr, b0,      b0 + 64,  1, W1 + 0 * 4096, F1pd };
    g1.j[2] = { outpW, outpC,   nullptr, b0,      b0 + 64,  1, W1 + 1 * 4096, F1pc };
    g1.j[3] = g1.j[4] = { nullptr, nullptr, nullptr, nullptr, nullptr, 0, nullptr, nullptr };
    g1.K = HID;
    gemm64_kernel<<<dim3(256, 3), 256>>>(g1);

    // L7: 4 layer-1 eler jobs
    E6 e1;
    e1.j[0] = { F1a,  al1 + 0 * 64, el1w };
    e1.j[1] = { F1pd, ar1 + 0 * 64, er1w };
    e1.j[2] = { F1pc, al1 + 1 * 64, el1c };
    e1.j[3] = { F1pc, ar1 + 1 * 64, er1c };
    e1.j[4] = e1.j[5] = { nullptr, nullptr, nullptr };
    eler_kernel<<<dim3(256, 4), 256>>>(e1);

    // L8: both layer-1 GATs batched (write separate partials)
    GatB gc;
    gc.j[0] = { rp_w, csr_w, el1w, er1w, F1a,  nullptr, 0, o1w };
    gc.j[1] = { rp_c, csr_c, el1c, er1c, F1pc, nullptr, 0, o1c };
    gc.j[2] = { nullptr, nullptr, nullptr, nullptr, nullptr, nullptr, 0, nullptr };
    gat_kernel<<<dim3(2048, 2), 256>>>(gc);

    // L9: hf (sums partials, inline scalar C, l2-normalized concat)
    hf_kernel<<<2048, 256>>>(o1w, o1c, b1, ln1_gb, attn_w, attn_b, ln2_gb,
                             ffn_w1, ffn_b1, ffn_w2, ffn_b2, hf);

    // L10: final projection
    gemm_full_kernel<<<dim3(256, 6), 256>>>(hf, lin_W, lin_b, out, 2 * HID, OUTF);
}